// round 12
// baseline (speedup 1.0000x reference)
#include <cuda_runtime.h>
#include <cuda_bf16.h>
#include <math.h>
#include <stdint.h>

#define NCLS 5
#define NQ   75
#define NN   80
#define FEAT 640
#define HID  4096
#define DIN  465
#define KPAD 512
#define LRC  1e-3f

// ------------------------- scratch (device globals) -------------------------
__device__ __align__(128) float g_supp[NCLS * FEAT];
__device__ __align__(128) float g_query[NQ * FEAT];
__device__ __align__(128) float g_F[NN * FEAT];          // normalized rows
__device__ float g_nrm[NN];
__device__ int   g_idx[NN * 81];
__device__ __align__(128) float g_G[NN * NN];
__device__ __align__(128) float g_parts[8 * NN * KPAD];
// activations, BLOCKED: A_blk[kb][80][64] bf16, SW128-swizzled 128B rows
__device__ __align__(1024) __nv_bfloat16 g_xb [NN * KPAD];
__device__ __align__(1024) __nv_bfloat16 g_h1b[NN * HID];
__device__ __align__(1024) __nv_bfloat16 g_h2b[NN * HID];
// weights, BLOCKED: W_blk[nb][kb][32][64] bf16, SW128-swizzled
__device__ __align__(1024) __nv_bfloat16 g_W1b[2][HID * KPAD];
__device__ __align__(1024) __nv_bfloat16 g_W2b[2][HID * HID];
__device__ __align__(1024) __nv_bfloat16 g_W3b[2][KPAD * HID];

#define SW128(o) ((o) ^ (((o) >> 3) & 0x70))
#define ABLK_OFF(m, k) (((k) >> 6) * 10240u + SW128((uint32_t)(((m) << 7) | (((k) & 63) << 1))))

__device__ __forceinline__ void mask_rc(int k, int& r, int& c) {
    int base;
    if      (k < 80)  { r = 0; base = 0;   }
    else if (k < 159) { r = 1; base = 80;  }
    else if (k < 237) { r = 2; base = 159; }
    else if (k < 314) { r = 3; base = 237; }
    else if (k < 390) { r = 4; base = 314; }
    else              { r = 5; base = 390; }
    c = r + 1 + (k - base);
}

// ------------------------- PTX helpers --------------------------------------
__device__ __forceinline__ uint32_t s_u32(const void* p) {
    return (uint32_t)__cvta_generic_to_shared(p);
}
__device__ __forceinline__ void ldsm_x4(uint32_t* r, uint32_t addr) {
    asm volatile("ldmatrix.sync.aligned.m8n8.x4.shared.b16 {%0,%1,%2,%3}, [%4];"
        : "=r"(r[0]), "=r"(r[1]), "=r"(r[2]), "=r"(r[3]) : "r"(addr));
}
__device__ __forceinline__ void ldsm_x2(uint32_t* r, uint32_t addr) {
    asm volatile("ldmatrix.sync.aligned.m8n8.x2.shared.b16 {%0,%1}, [%2];"
        : "=r"(r[0]), "=r"(r[1]) : "r"(addr));
}
__device__ __forceinline__ void mma_bf16(float* d, const uint32_t* a, const uint32_t* b) {
    asm volatile("mma.sync.aligned.m16n8k16.row.col.f32.bf16.bf16.f32 "
        "{%0,%1,%2,%3}, {%4,%5,%6,%7}, {%8,%9}, {%0,%1,%2,%3};"
        : "+f"(d[0]), "+f"(d[1]), "+f"(d[2]), "+f"(d[3])
        : "r"(a[0]), "r"(a[1]), "r"(a[2]), "r"(a[3]), "r"(b[0]), "r"(b[1]));
}
__device__ __forceinline__ void bulkcp(uint32_t dst, const void* src, uint32_t bytes,
                                       uint32_t mbar) {
    asm volatile(
        "cp.async.bulk.shared::cluster.global.mbarrier::complete_tx::bytes [%0], [%1], %2, [%3];"
        :: "r"(dst), "l"(src), "r"(bytes), "r"(mbar) : "memory");
}
__device__ __forceinline__ void mbar_init(uint32_t mbar, uint32_t cnt) {
    asm volatile("mbarrier.init.shared.b64 [%0], %1;" :: "r"(mbar), "r"(cnt) : "memory");
}
__device__ __forceinline__ void mbar_expect(uint32_t mbar, uint32_t tx) {
    asm volatile("mbarrier.arrive.expect_tx.shared.b64 _, [%0], %1;"
                 :: "r"(mbar), "r"(tx) : "memory");
}
#define MWAIT(addr, ph) do { \
    uint32_t _d = 0; \
    while (!_d) { \
        asm volatile("{\n\t.reg .pred p;\n\t" \
            "mbarrier.try_wait.parity.acquire.cta.shared::cta.b64 p, [%1], %2;\n\t" \
            "selp.b32 %0, 1, 0, p;\n\t}" : "=r"(_d) : "r"(addr), "r"(ph)); \
    } } while (0)

// --- merged: blocks 0..19 do init (supp mean/query copy); rest convert W ----
#define T1 2097152
#define T2 16777216
#define T3 2097152
#define CONVBLK 10240      // conv blocks (256 thr, 8 elems/thr)
__global__ void k_convinit(const float* fs, const float* fq,
                           const float* s0, const float* s1, const float* s2,
                           const float* s3, const float* s4, const float* s5) {
    if (blockIdx.x < 20) {   // init: 20 blocks x 256 = 5120 threads >= needed rows chunk
        for (int idx = blockIdx.x * 256 + threadIdx.x; idx < NN * FEAT; idx += 20 * 256) {
            int r = idx / FEAT, d = idx % FEAT;
            if (r < NCLS) {
                float s = 0.f;
                #pragma unroll
                for (int sh = 0; sh < 5; sh++) s += fs[(r * 5 + sh) * FEAT + d];
                g_supp[r * FEAT + d] = s / 5.0f;
            } else {
                g_query[(r - NCLS) * FEAT + d] = fq[(r - NCLS) * FEAT + d];
            }
        }
        return;
    }
    long long e = (long long)(blockIdx.x - 20) * 2048 + (long long)threadIdx.x * 8;
    const float* src; char* dst; long long local; int type;
    if      (e < T1)           { src = s0; dst = (char*)g_W1b[0]; local = e;                  type = 0; }
    else if (e < T1+T2)        { src = s1; dst = (char*)g_W2b[0]; local = e - T1;             type = 1; }
    else if (e < T1+T2+T3)     { src = s2; dst = (char*)g_W3b[0]; local = e - (T1+T2);        type = 2; }
    else if (e < 2*T1+T2+T3)   { src = s3; dst = (char*)g_W1b[1]; local = e - (T1+T2+T3);     type = 0; }
    else if (e < 2*T1+2*T2+T3) { src = s4; dst = (char*)g_W2b[1]; local = e - (2*T1+T2+T3);   type = 1; }
    else                       { src = s5; dst = (char*)g_W3b[1]; local = e - (2*T1+2*T2+T3); type = 2; }
    int K = (type == 0) ? 512 : 4096;
    int n = (int)(local / K);
    int k = (int)(local - (long long)n * K);
    float v[8];
    #pragma unroll
    for (int j = 0; j < 8; j++) {
        bool ok = (type == 0) ? (k + j < DIN) : (type == 2 ? (n < DIN) : true);
        int cols = (type == 0) ? DIN : 4096;
        v[j] = ok ? src[(size_t)n * cols + k + j] : 0.f;
    }
    uint32_t off = ((uint32_t)(n >> 5) * (uint32_t)(K >> 6) + (uint32_t)(k >> 6)) * 4096u
                 + SW128((uint32_t)(((n & 31) << 7) | ((k & 63) << 1)));
    uint32_t o[4];
    #pragma unroll
    for (int j = 0; j < 4; j++) {
        __nv_bfloat162 h;
        h.x = __float2bfloat16(v[2 * j]);
        h.y = __float2bfloat16(v[2 * j + 1]);
        o[j] = *(uint32_t*)&h;
    }
    *(uint4*)(dst + off) = make_uint4(o[0], o[1], o[2], o[3]);
}

// ---------------- norm: raw rows -> g_F (normalized) + g_nrm ----------------
__global__ void k_norm() {
    int i = blockIdx.x;              // 80 blocks x 256
    int tid = threadIdx.x;
    __shared__ float red[256];
    const float* src = (i < NCLS) ? (g_supp + i * FEAT) : (g_query + (i - NCLS) * FEAT);
    float s = 0.f;
    for (int d = tid; d < FEAT; d += 256) { float v = src[d]; s += v * v; }
    red[tid] = s; __syncthreads();
    for (int o = 128; o > 0; o >>= 1) { if (tid < o) red[tid] += red[tid + o]; __syncthreads(); }
    float nrm = fmaxf(sqrtf(red[0]), 1e-12f);
    if (tid == 0) g_nrm[i] = nrm;
    float inv = 1.f / nrm;
    for (int d = tid; d < FEAT; d += 256) g_F[i * FEAT + d] = src[d] * inv;
}

// ---- simsort: 6 needed sim rows from g_F + rank sort + gather + zero G -----
__global__ void k_simsort() {
    int i = blockIdx.x;              // 80 blocks x 256
    int tid = threadIdx.x;
    int w = tid >> 5, l = tid & 31;
    __shared__ float sF[6 * FEAT];   // row 0 = i, rows 1..5 = supp 0..4
    __shared__ float srow[6 * NN];
    __shared__ int a[81];
    for (int t = tid; t < 6 * FEAT; t += 256) {
        int rr = t / FEAT, d = t - rr * FEAT;
        int row = (rr == 0) ? i : (rr - 1);
        sF[t] = g_F[row * FEAT + d];
    }
    if (tid == 0) a[0] = i;
    __syncthreads();
    for (int j = w; j < NN; j += 8) {
        float acc[6] = {0.f, 0.f, 0.f, 0.f, 0.f, 0.f};
        const float* Fj = g_F + j * FEAT;
        for (int d = l; d < FEAT; d += 32) {
            float fj = Fj[d];
            #pragma unroll
            for (int rr = 0; rr < 6; rr++) acc[rr] += sF[rr * FEAT + d] * fj;
        }
        #pragma unroll
        for (int rr = 0; rr < 6; rr++) {
            #pragma unroll
            for (int o = 16; o > 0; o >>= 1)
                acc[rr] += __shfl_xor_sync(0xffffffffu, acc[rr], o);
        }
        if (l == 0) {
            #pragma unroll
            for (int rr = 0; rr < 6; rr++) srow[rr * NN + j] = acc[rr];
        }
    }
    __syncthreads();
    if (tid < NCLS) {                // stable-descending rank, support keys
        float v = srow[tid];
        int rank = 0;
        #pragma unroll
        for (int j = 0; j < NCLS; j++) {
            float u = srow[j];
            if (j != tid && (u > v || (u == v && j < tid))) rank++;
        }
        a[1 + rank] = tid;
    }
    if (tid < NQ) {                  // query keys
        float v = srow[NCLS + tid];
        int rank = 0;
        for (int j = 0; j < NQ; j++) {
            float u = srow[NCLS + j];
            if (u > v || (u == v && j < tid)) rank++;
        }
        a[6 + rank] = NCLS + tid;
    }
    __syncthreads();
    for (int t = tid; t < 81; t += 256) g_idx[i * 81 + t] = a[t];
    char* xb = (char*)g_xb;
    for (int k = tid; k < KPAD; k += 256) {
        float v = 0.f;
        if (k < DIN) {
            int r, c; mask_rc(k, r, c);
            int rrow = (r == 0) ? 0 : (1 + a[r]);
            v = srow[rrow * NN + a[c]];
        }
        *(__nv_bfloat16*)(xb + ABLK_OFF(i, k)) = __float2bfloat16(v);
    }
    for (int t = tid; t < NN; t += 256) g_G[i * NN + t] = 0.f;
}

// ========= bulk-loaded mma.sync GEMM: 512 thr, 4 kgroups x 4 n-warps ========
// D[80 x 32] = A[80 x Kchunk] * W[32 x Kchunk]^T at (nb=blockIdx.x, sk=blockIdx.y)
// stage = 4 x [A 10240 | W 4096] = 57344B, 3 stages.
#define KGB 14336
#define STB 57344
#define GSMEM (3 * STB + 1024)
template<int MODE>
__global__ void __launch_bounds__(512) k_gemmB(
    const char* __restrict__ Ablk, const char* __restrict__ Wblk,
    int KbTotal, int Kchunk, const float* __restrict__ bias,
    void* __restrict__ Cout, int partStride)
{
    extern __shared__ char dyn[];
    __shared__ uint64_t mbar[3];
    const int tid = threadIdx.x, w = tid >> 5, l = tid & 31;
    const int kg = w >> 2, nw = w & 3;
    const int nb = blockIdx.x;
    const int k0 = blockIdx.y * Kchunk;
    const int kgK = Kchunk >> 2;
    const int nIt = kgK >> 6;
    const uint32_t sbase = (s_u32(dyn) + 1023u) & ~1023u;
    char* dalign = (char*)(((uintptr_t)dyn + 1023ull) & ~1023ull);

    if (tid == 0) {
        #pragma unroll
        for (int i = 0; i < 3; i++) mbar_init(s_u32(&mbar[i]), 1);
    }
    __syncthreads();

    auto issue = [&](int it, int s) {
        uint32_t st = sbase + s * STB;
        uint32_t mb = s_u32(&mbar[s]);
        mbar_expect(mb, STB);
        #pragma unroll
        for (int g = 0; g < 4; g++) {
            int kb = ((k0 + g * kgK) >> 6) + it;
            bulkcp(st + g * KGB,         Ablk + (size_t)kb * 10240, 10240, mb);
            bulkcp(st + g * KGB + 10240, Wblk + ((size_t)nb * KbTotal + kb) * 4096, 4096, mb);
        }
    };

    if (tid == 0) {
        int npre = (nIt < 3) ? nIt : 3;
        for (int c = 0; c < npre; c++) issue(c, c);
    }

    float acc[5][4];
    #pragma unroll
    for (int mt = 0; mt < 5; mt++)
        #pragma unroll
        for (int q = 0; q < 4; q++) acc[mt][q] = 0.f;

    const int arow = (l & 7) + 8 * ((l >> 3) & 1);
    const int acolB = 16 * (l >> 4);
    const int brow = (l & 7);
    const int bcolB = 16 * ((l >> 3) & 1);

    int ph[3] = {0, 0, 0};
    for (int it = 0; it < nIt; it++) {
        int s = it % 3;
        MWAIT(s_u32(&mbar[s]), ph[s]); ph[s] ^= 1;
        uint32_t A0 = sbase + s * STB + kg * KGB;
        uint32_t W0 = A0 + 10240;
        #pragma unroll
        for (int ks = 0; ks < 4; ks++) {
            uint32_t kb = ks * 32;
            uint32_t b[2];
            ldsm_x2(b, W0 + SW128((uint32_t)((nw * 8 + brow) * 128) + kb + bcolB));
            #pragma unroll
            for (int mt = 0; mt < 5; mt++) {
                uint32_t a[4];
                ldsm_x4(a, A0 + SW128((uint32_t)((mt * 16 + arow) * 128) + kb + acolB));
                mma_bf16(acc[mt], a, b);
            }
        }
        __syncthreads();
        if (tid == 0 && it + 3 < nIt) issue(it + 3, s);
    }

    // reduce 4 kgroups: kg 1..3 write scratch, kg 0 accumulates + stores
    float* scr = (float*)dalign;   // 3 x 2560 floats = 30KB
    __syncthreads();
    if (kg > 0) {
        float* sp = scr + (kg - 1) * 2560;
        #pragma unroll
        for (int mt = 0; mt < 5; mt++)
            #pragma unroll
            for (int q = 0; q < 4; q++)
                sp[((nw * 5 + mt) * 32 + l) * 4 + q] = acc[mt][q];
    }
    __syncthreads();
    if (kg == 0) {
        int n = nb * 32 + nw * 8 + 2 * (l & 3);
        #pragma unroll
        for (int mt = 0; mt < 5; mt++) {
            float v[4];
            #pragma unroll
            for (int q = 0; q < 4; q++) {
                int idx = ((nw * 5 + mt) * 32 + l) * 4 + q;
                v[q] = acc[mt][q] + scr[idx] + scr[2560 + idx] + scr[5120 + idx];
            }
            int m0 = mt * 16 + (l >> 2);
            if (MODE == 0) {
                char* H = (char*)Cout;
                float b0 = bias[n], b1 = bias[n + 1];
                __nv_bfloat162 h0, h1;
                h0.x = __float2bfloat16(fmaxf(v[0] + b0, 0.f));
                h0.y = __float2bfloat16(fmaxf(v[1] + b1, 0.f));
                h1.x = __float2bfloat16(fmaxf(v[2] + b0, 0.f));
                h1.y = __float2bfloat16(fmaxf(v[3] + b1, 0.f));
                *(__nv_bfloat162*)(H + ABLK_OFF(m0, n))     = h0;
                *(__nv_bfloat162*)(H + ABLK_OFF(m0 + 8, n)) = h1;
            } else {
                float* Cp = (float*)Cout + (size_t)blockIdx.y * partStride;
                *(float2*)&Cp[(size_t)m0 * KPAD + n]       = make_float2(v[0], v[1]);
                *(float2*)&Cp[(size_t)(m0 + 8) * KPAD + n] = make_float2(v[2], v[3]);
            }
        }
    }
}

// ------ scatter: G += g at (a_r,a_c),(a_c,a_r); g = sum8(parts)+b3 ----------
__global__ void k_scatter(const float* __restrict__ b3) {
    int i = blockIdx.x;
    int tid = threadIdx.x;   // 128
    __shared__ int a[81];
    for (int t = tid; t < 81; t += 128) a[t] = g_idx[i * 81 + t];
    __syncthreads();
    for (int k = tid; k < DIN; k += 128) {
        float v = b3[k];
        #pragma unroll
        for (int s = 0; s < 8; s++) v += g_parts[(size_t)s * NN * KPAD + i * KPAD + k];
        int r, c; mask_rc(k, r, c);
        atomicAdd(&g_G[a[r] * NN + a[c]], v);
        atomicAdd(&g_G[a[c] * NN + a[r]], v);
    }
}

// --------- Fbar = Gbar F; normalize-VJP; SGD update; renorm row -------------
__global__ void k_update(int lo, float* __restrict__ target) {
    int p = lo + blockIdx.x;
    int tid = threadIdx.x;
    __shared__ float Gp[NN];
    __shared__ float fb[FEAT];
    __shared__ float red[256];
    for (int q = tid; q < NN; q += 256) Gp[q] = g_G[p * NN + q];
    __syncthreads();
    for (int d = tid; d < FEAT; d += 256) {
        float s = 0.f;
        #pragma unroll 8
        for (int q = 0; q < NN; q++) s += Gp[q] * g_F[q * FEAT + d];
        fb[d] = s;
    }
    __syncthreads();
    float part = 0.f;
    for (int d = tid; d < FEAT; d += 256) part += fb[d] * g_F[p * FEAT + d];
    red[tid] = part; __syncthreads();
    for (int o = 128; o > 0; o >>= 1) { if (tid < o) red[tid] += red[tid + o]; __syncthreads(); }
    float dot = red[0];
    float inv = 1.f / g_nrm[p];
    for (int d = tid; d < FEAT; d += 256) {
        float fp = g_F[p * FEAT + d];
        float dX = (fb[d] - dot * fp) * inv;
        target[(p - lo) * FEAT + d] -= LRC * dX;
    }
}

// ------------- final: normalize from raw + (sim_sq * scale)^T ---------------
__global__ void k_final(const float* __restrict__ scale, float* __restrict__ out) {
    int q = blockIdx.x;
    int tid = threadIdx.x;
    __shared__ float Fq[FEAT];
    __shared__ float red[256];
    const float* qr = g_query + q * FEAT;
    float s = 0.f;
    for (int d = tid; d < FEAT; d += 256) { float v = qr[d]; Fq[d] = v; s += v * v; }
    red[tid] = s; __syncthreads();
    for (int o = 128; o > 0; o >>= 1) { if (tid < o) red[tid] += red[tid + o]; __syncthreads(); }
    float nq = fmaxf(sqrtf(red[0]), 1e-12f);
    int w = tid >> 5, l = tid & 31;
    if (w < NCLS) {
        const float* sr = g_supp + w * FEAT;
        float dt = 0.f, s2 = 0.f;
        for (int d = l; d < FEAT; d += 32) {
            float sv = sr[d];
            dt += sv * Fq[d];
            s2 += sv * sv;
        }
        #pragma unroll
        for (int o = 16; o > 0; o >>= 1) {
            dt += __shfl_xor_sync(0xffffffffu, dt, o);
            s2 += __shfl_xor_sync(0xffffffffu, s2, o);
        }
        if (l == 0) {
            float ns = fmaxf(sqrtf(s2), 1e-12f);
            out[q * NCLS + w] = dt / (ns * nq) * scale[0];
        }
    }
}

// ----------------------------------------------------------------------------
extern "C" void kernel_launch(void* const* d_in, const int* in_sizes, int n_in,
                              void* d_out, int out_size) {
    const float* fs    = (const float*)d_in[0];
    const float* fq    = (const float*)d_in[1];
    const float* scale = (const float*)d_in[2];

    float *pp, *ps, *pq;
    char *pxb, *ph1b, *ph2b, *pw1b, *pw2b, *pw3b;
    cudaGetSymbolAddress((void**)&pp,   g_parts);
    cudaGetSymbolAddress((void**)&ps,   g_supp);
    cudaGetSymbolAddress((void**)&pq,   g_query);
    cudaGetSymbolAddress((void**)&pxb,  g_xb);
    cudaGetSymbolAddress((void**)&ph1b, g_h1b);
    cudaGetSymbolAddress((void**)&ph2b, g_h2b);
    cudaGetSymbolAddress((void**)&pw1b, g_W1b);
    cudaGetSymbolAddress((void**)&pw2b, g_W2b);
    cudaGetSymbolAddress((void**)&pw3b, g_W3b);

    cudaFuncSetAttribute(k_gemmB<0>, cudaFuncAttributeMaxDynamicSharedMemorySize, GSMEM);
    cudaFuncSetAttribute(k_gemmB<1>, cudaFuncAttributeMaxDynamicSharedMemorySize, GSMEM);

    // merged init + weight conversion (independent writes)
    k_convinit<<<20 + CONVBLK, 256>>>(fs, fq,
        (const float*)d_in[3],  (const float*)d_in[5],  (const float*)d_in[7],
        (const float*)d_in[9],  (const float*)d_in[11], (const float*)d_in[13]);
    k_norm<<<NN, 256>>>();

    for (int step = 0; step < 3; step++) {
        for (int br = 0; br < 2; br++) {
            const float* b1 = (const float*)d_in[3 + 6 * br + 1];
            const float* b2 = (const float*)d_in[3 + 6 * br + 3];
            const float* b3 = (const float*)d_in[3 + 6 * br + 5];
            char* W1b = pw1b + (size_t)br * T1 * 2;
            char* W2b = pw2b + (size_t)br * T2 * 2;
            char* W3b = pw3b + (size_t)br * T3 * 2;
            int lo    = br ? NCLS : 0;
            int nrows = br ? NQ : NCLS;
            float* target = br ? pq : ps;

            k_simsort<<<NN, 256>>>();
            // L1: K=512 (kgK=128, nIt=2), N=4096 -> 128 n-blocks
            k_gemmB<0><<<dim3(128, 1), 512, GSMEM>>>(pxb, W1b, 8, 512, b1, ph1b, 0);
            // L2: K=4096 (kgK=1024, nIt=16), N=4096
            k_gemmB<0><<<dim3(128, 1), 512, GSMEM>>>(ph1b, W2b, 64, 4096, b2, ph2b, 0);
            // L3: N=512 (16 n-blocks), splitK=8 (Kchunk=512)
            k_gemmB<1><<<dim3(16, 8), 512, GSMEM>>>(ph2b, W3b, 64, 512, nullptr, pp, NN * KPAD);
            k_scatter<<<NN, 128>>>(b3);
            k_update<<<nrows, 256>>>(lo, target);

            // renorm changed rows for next simsort (fold into norm kernel)
            k_norm<<<NN, 256>>>();
        }
    }

    k_final<<<NQ, 256>>>(scale, (float*)d_out);
}

// round 13
// speedup vs baseline: 1.1506x; 1.1506x over previous
#include <cuda_runtime.h>
#include <cuda_bf16.h>
#include <math.h>
#include <stdint.h>

#define NCLS 5
#define NQ   75
#define NN   80
#define FEAT 640
#define HID  4096
#define DIN  465
#define KPAD 512
#define LRC  1e-3f

// ------------------------- scratch (device globals) -------------------------
__device__ __align__(128) float g_supp[NCLS * FEAT];
__device__ __align__(128) float g_query[NQ * FEAT];
__device__ __align__(128) float g_F[NN * FEAT];          // normalized rows
__device__ float g_nrm[NN];
__device__ __align__(128) float g_sim[NN * NN];          // RAW dot products
__device__ int   g_idx[NN * 81];
__device__ __align__(128) float g_G[NN * NN];
__device__ __align__(128) float g_parts[8 * NN * KPAD];
// activations, BLOCKED: A_blk[kb][80][64] bf16, SW128-swizzled 128B rows
__device__ __align__(1024) __nv_bfloat16 g_xb [NN * KPAD];
__device__ __align__(1024) __nv_bfloat16 g_h1b[NN * HID];
__device__ __align__(1024) __nv_bfloat16 g_h2b[NN * HID];
// weights, BLOCKED: W_blk[nb][kb][32][64] bf16, SW128-swizzled
__device__ __align__(1024) __nv_bfloat16 g_W1b[2][HID * KPAD];
__device__ __align__(1024) __nv_bfloat16 g_W2b[2][HID * HID];
__device__ __align__(1024) __nv_bfloat16 g_W3b[2][KPAD * HID];

#define SW128(o) ((o) ^ (((o) >> 3) & 0x70))
#define ABLK_OFF(m, k) (((k) >> 6) * 10240u + SW128((uint32_t)(((m) << 7) | (((k) & 63) << 1))))

// PDL intrinsics (sm_90+)
#define GD_LAUNCH asm volatile("griddepcontrol.launch_dependents;")
#define GD_WAIT   asm volatile("griddepcontrol.wait;" ::: "memory")

__device__ __forceinline__ void mask_rc(int k, int& r, int& c) {
    int base;
    if      (k < 80)  { r = 0; base = 0;   }
    else if (k < 159) { r = 1; base = 80;  }
    else if (k < 237) { r = 2; base = 159; }
    else if (k < 314) { r = 3; base = 237; }
    else if (k < 390) { r = 4; base = 314; }
    else              { r = 5; base = 390; }
    c = r + 1 + (k - base);
}

// ------------------------- PTX helpers --------------------------------------
__device__ __forceinline__ uint32_t s_u32(const void* p) {
    return (uint32_t)__cvta_generic_to_shared(p);
}
__device__ __forceinline__ void ldsm_x4(uint32_t* r, uint32_t addr) {
    asm volatile("ldmatrix.sync.aligned.m8n8.x4.shared.b16 {%0,%1,%2,%3}, [%4];"
        : "=r"(r[0]), "=r"(r[1]), "=r"(r[2]), "=r"(r[3]) : "r"(addr));
}
__device__ __forceinline__ void ldsm_x2(uint32_t* r, uint32_t addr) {
    asm volatile("ldmatrix.sync.aligned.m8n8.x2.shared.b16 {%0,%1}, [%2];"
        : "=r"(r[0]), "=r"(r[1]) : "r"(addr));
}
__device__ __forceinline__ void mma_bf16(float* d, const uint32_t* a, const uint32_t* b) {
    asm volatile("mma.sync.aligned.m16n8k16.row.col.f32.bf16.bf16.f32 "
        "{%0,%1,%2,%3}, {%4,%5,%6,%7}, {%8,%9}, {%0,%1,%2,%3};"
        : "+f"(d[0]), "+f"(d[1]), "+f"(d[2]), "+f"(d[3])
        : "r"(a[0]), "r"(a[1]), "r"(a[2]), "r"(a[3]), "r"(b[0]), "r"(b[1]));
}
__device__ __forceinline__ void bulkcp(uint32_t dst, const void* src, uint32_t bytes,
                                       uint32_t mbar) {
    asm volatile(
        "cp.async.bulk.shared::cluster.global.mbarrier::complete_tx::bytes [%0], [%1], %2, [%3];"
        :: "r"(dst), "l"(src), "r"(bytes), "r"(mbar) : "memory");
}
__device__ __forceinline__ void mbar_init(uint32_t mbar, uint32_t cnt) {
    asm volatile("mbarrier.init.shared.b64 [%0], %1;" :: "r"(mbar), "r"(cnt) : "memory");
}
__device__ __forceinline__ void mbar_expect(uint32_t mbar, uint32_t tx) {
    asm volatile("mbarrier.arrive.expect_tx.shared.b64 _, [%0], %1;"
                 :: "r"(mbar), "r"(tx) : "memory");
}
#define MWAIT(addr, ph) do { \
    uint32_t _d = 0; \
    while (!_d) { \
        asm volatile("{\n\t.reg .pred p;\n\t" \
            "mbarrier.try_wait.parity.acquire.cta.shared::cta.b64 p, [%1], %2;\n\t" \
            "selp.b32 %0, 1, 0, p;\n\t}" : "=r"(_d) : "r"(addr), "r"(ph)); \
    } } while (0)

// ---- merged FIRST kernel: blocks 0..19 init raw rows, rest convert weights -
// (no GD_LAUNCH: implicit trigger at completion gates the whole PDL cascade)
#define T1 2097152
#define T2 16777216
#define T3 2097152
#define CONVBLK 20480
__global__ void k_convinit(const float* fs, const float* fq,
                           const float* s0, const float* s1, const float* s2,
                           const float* s3, const float* s4, const float* s5) {
    if (blockIdx.x < 20) {
        for (int idx = blockIdx.x * 256 + threadIdx.x; idx < NN * FEAT; idx += 20 * 256) {
            int r = idx / FEAT, d = idx % FEAT;
            if (r < NCLS) {
                float s = 0.f;
                #pragma unroll
                for (int sh = 0; sh < 5; sh++) s += fs[(r * 5 + sh) * FEAT + d];
                g_supp[r * FEAT + d] = s / 5.0f;
            } else {
                g_query[(r - NCLS) * FEAT + d] = fq[(r - NCLS) * FEAT + d];
            }
        }
        return;
    }
    long long e = ((long long)(blockIdx.x - 20) * 256 + threadIdx.x) * 8;
    const float* src; char* dst; long long local; int type;
    if      (e < T1)           { src = s0; dst = (char*)g_W1b[0]; local = e;                  type = 0; }
    else if (e < T1+T2)        { src = s1; dst = (char*)g_W2b[0]; local = e - T1;             type = 1; }
    else if (e < T1+T2+T3)     { src = s2; dst = (char*)g_W3b[0]; local = e - (T1+T2);        type = 2; }
    else if (e < 2*T1+T2+T3)   { src = s3; dst = (char*)g_W1b[1]; local = e - (T1+T2+T3);     type = 0; }
    else if (e < 2*T1+2*T2+T3) { src = s4; dst = (char*)g_W2b[1]; local = e - (2*T1+T2+T3);   type = 1; }
    else                       { src = s5; dst = (char*)g_W3b[1]; local = e - (2*T1+2*T2+T3); type = 2; }
    int K = (type == 0) ? 512 : 4096;
    int n = (int)(local / K);
    int k = (int)(local - (long long)n * K);
    float v[8];
    #pragma unroll
    for (int j = 0; j < 8; j++) {
        bool ok = (type == 0) ? (k + j < DIN) : (type == 2 ? (n < DIN) : true);
        int cols = (type == 0) ? DIN : 4096;
        v[j] = ok ? src[(size_t)n * cols + k + j] : 0.f;
    }
    uint32_t off = ((uint32_t)(n >> 5) * (uint32_t)(K >> 6) + (uint32_t)(k >> 6)) * 4096u
                 + SW128((uint32_t)(((n & 31) << 7) | ((k & 63) << 1)));
    uint32_t o[4];
    #pragma unroll
    for (int j = 0; j < 4; j++) {
        __nv_bfloat162 h;
        h.x = __float2bfloat16(v[2 * j]);
        h.y = __float2bfloat16(v[2 * j + 1]);
        o[j] = *(uint32_t*)&h;
    }
    *(uint4*)(dst + off) = make_uint4(o[0], o[1], o[2], o[3]);
}

// ---------- sim: raw Gram row + own norm + normalized F row -----------------
__global__ void k_sim() {
    GD_LAUNCH; GD_WAIT;
    int i = blockIdx.x;
    int tid = threadIdx.x;
    __shared__ float Fi[FEAT];
    __shared__ float red[256];
    const float* src = (i < NCLS) ? (g_supp + i * FEAT) : (g_query + (i - NCLS) * FEAT);
    float s = 0.f;
    for (int d = tid; d < FEAT; d += 256) { float v = src[d]; Fi[d] = v; s += v * v; }
    red[tid] = s; __syncthreads();
    for (int o = 128; o > 0; o >>= 1) { if (tid < o) red[tid] += red[tid + o]; __syncthreads(); }
    float nrm = fmaxf(sqrtf(red[0]), 1e-12f);
    if (tid == 0) g_nrm[i] = nrm;
    float inv = 1.f / nrm;
    for (int d = tid; d < FEAT; d += 256) g_F[i * FEAT + d] = Fi[d] * inv;
    int w = tid >> 5, l = tid & 31;
    for (int j = w; j < NN; j += 8) {
        const float* Xj = (j < NCLS) ? (g_supp + j * FEAT) : (g_query + (j - NCLS) * FEAT);
        float p = 0.f;
        for (int d = l; d < FEAT; d += 32) p += Fi[d] * Xj[d];
        #pragma unroll
        for (int o = 16; o > 0; o >>= 1) p += __shfl_xor_sync(0xffffffffu, p, o);
        if (l == 0) g_sim[i * NN + j] = p;
    }
}

// ------- stable rank sort + gather DNI inputs into BLOCKED bf16 -------------
__global__ void k_sortgather() {
    GD_LAUNCH; GD_WAIT;
    int i = blockIdx.x;
    int tid = threadIdx.x;   // 128
    __shared__ float srow[NN];
    __shared__ float inv[NN];
    __shared__ int a[81];
    for (int j = tid; j < NN; j += 128) inv[j] = 1.f / g_nrm[j];
    __syncthreads();
    float invi = inv[i];
    for (int j = tid; j < NN; j += 128) srow[j] = g_sim[i * NN + j] * invi * inv[j];
    if (tid == 0) a[0] = i;
    __syncthreads();
    if (tid < NCLS) {
        float v = srow[tid];
        int rank = 0;
        #pragma unroll
        for (int j = 0; j < NCLS; j++) {
            float u = srow[j];
            if (j != tid && (u > v || (u == v && j < tid))) rank++;
        }
        a[1 + rank] = tid;
    }
    if (tid < NQ) {
        float v = srow[NCLS + tid];
        int rank = 0;
        for (int j = 0; j < NQ; j++) {
            float u = srow[NCLS + j];
            if (u > v || (u == v && j < tid)) rank++;
        }
        a[6 + rank] = NCLS + tid;
    }
    __syncthreads();
    for (int t = tid; t < 81; t += 128) g_idx[i * 81 + t] = a[t];
    char* xb = (char*)g_xb;
    for (int k = tid; k < KPAD; k += 128) {
        float v = 0.f;
        if (k < DIN) {
            int r, c; mask_rc(k, r, c);
            v = g_sim[a[r] * NN + a[c]] * inv[a[r]] * inv[a[c]];
        }
        *(__nv_bfloat16*)(xb + ABLK_OFF(i, k)) = __float2bfloat16(v);
    }
    for (int t = tid; t < NN; t += 128) g_G[i * NN + t] = 0.f;
}

// ========= bulk-loaded mma.sync GEMM: 512 thr, 4 kgroups x 4 n-warps ========
// D[80 x 32] = A[80 x Kchunk] * W[32 x Kchunk]^T at (nb=blockIdx.x, sk=blockIdx.y)
// stage = 4 x [A 10240 | W 4096] = 57344B, 3 stages. W prefetched pre-GD_WAIT.
#define KGB 14336
#define STB 57344
#define GSMEM (3 * STB + 1024)
template<int MODE>
__global__ void __launch_bounds__(512) k_gemmB(
    const char* __restrict__ Ablk, const char* __restrict__ Wblk,
    int KbTotal, int Kchunk, const float* __restrict__ bias,
    void* __restrict__ Cout, int partStride)
{
    extern __shared__ char dyn[];
    __shared__ uint64_t mbarW[3], mbarA[3];
    GD_LAUNCH;
    const int tid = threadIdx.x, w = tid >> 5, l = tid & 31;
    const int kg = w >> 2, nw = w & 3;
    const int nb = blockIdx.x;
    const int k0 = blockIdx.y * Kchunk;
    const int kgK = Kchunk >> 2;
    const int nIt = kgK >> 6;
    const uint32_t sbase = (s_u32(dyn) + 1023u) & ~1023u;
    char* dalign = (char*)(((uintptr_t)dyn + 1023ull) & ~1023ull);

    if (tid == 0) {
        #pragma unroll
        for (int i = 0; i < 3; i++) {
            mbar_init(s_u32(&mbarW[i]), 1);
            mbar_init(s_u32(&mbarA[i]), 1);
        }
    }
    __syncthreads();

    auto issueW = [&](int it, int s) {
        uint32_t st = sbase + s * STB;
        uint32_t mb = s_u32(&mbarW[s]);
        mbar_expect(mb, 4 * 4096);
        #pragma unroll
        for (int g = 0; g < 4; g++) {
            int kb = ((k0 + g * kgK) >> 6) + it;
            bulkcp(st + g * KGB + 10240, Wblk + ((size_t)nb * KbTotal + kb) * 4096, 4096, mb);
        }
    };
    auto issueA = [&](int it, int s) {
        uint32_t st = sbase + s * STB;
        uint32_t mb = s_u32(&mbarA[s]);
        mbar_expect(mb, 4 * 10240);
        #pragma unroll
        for (int g = 0; g < 4; g++) {
            int kb = ((k0 + g * kgK) >> 6) + it;
            bulkcp(st + g * KGB, Ablk + (size_t)kb * 10240, 10240, mb);
        }
    };

    int npre = (nIt < 3) ? nIt : 3;
    if (tid == 0)                               // W is static: prefetch BEFORE wait
        for (int c = 0; c < npre; c++) issueW(c, c);
    GD_WAIT;                                     // upstream (A producer) complete
    if (tid == 0)
        for (int c = 0; c < npre; c++) issueA(c, c);

    float acc[5][4];
    #pragma unroll
    for (int mt = 0; mt < 5; mt++)
        #pragma unroll
        for (int q = 0; q < 4; q++) acc[mt][q] = 0.f;

    const int arow = (l & 7) + 8 * ((l >> 3) & 1);
    const int acolB = 16 * (l >> 4);
    const int brow = (l & 7);
    const int bcolB = 16 * ((l >> 3) & 1);

    int phW[3] = {0, 0, 0}, phA[3] = {0, 0, 0};
    for (int it = 0; it < nIt; it++) {
        int s = it % 3;
        MWAIT(s_u32(&mbarW[s]), phW[s]); phW[s] ^= 1;
        MWAIT(s_u32(&mbarA[s]), phA[s]); phA[s] ^= 1;
        uint32_t A0 = sbase + s * STB + kg * KGB;
        uint32_t W0 = A0 + 10240;
        #pragma unroll
        for (int ks = 0; ks < 4; ks++) {
            uint32_t kb = ks * 32;
            uint32_t b[2];
            ldsm_x2(b, W0 + SW128((uint32_t)((nw * 8 + brow) * 128) + kb + bcolB));
            #pragma unroll
            for (int mt = 0; mt < 5; mt++) {
                uint32_t a[4];
                ldsm_x4(a, A0 + SW128((uint32_t)((mt * 16 + arow) * 128) + kb + acolB));
                mma_bf16(acc[mt], a, b);
            }
        }
        __syncthreads();
        if (tid == 0 && it + 3 < nIt) { issueW(it + 3, s); issueA(it + 3, s); }
    }

    // reduce 4 kgroups: kg 1..3 write scratch, kg 0 accumulates + stores
    float* scr = (float*)dalign;   // 3 x 2560 floats = 30KB
    __syncthreads();
    if (kg > 0) {
        float* sp = scr + (kg - 1) * 2560;
        #pragma unroll
        for (int mt = 0; mt < 5; mt++)
            #pragma unroll
            for (int q = 0; q < 4; q++)
                sp[((nw * 5 + mt) * 32 + l) * 4 + q] = acc[mt][q];
    }
    __syncthreads();
    if (kg == 0) {
        int n = nb * 32 + nw * 8 + 2 * (l & 3);
        #pragma unroll
        for (int mt = 0; mt < 5; mt++) {
            float v[4];
            #pragma unroll
            for (int q = 0; q < 4; q++) {
                int idx = ((nw * 5 + mt) * 32 + l) * 4 + q;
                v[q] = acc[mt][q] + scr[idx] + scr[2560 + idx] + scr[5120 + idx];
            }
            int m0 = mt * 16 + (l >> 2);
            if (MODE == 0) {
                char* H = (char*)Cout;
                float b0 = bias[n], b1 = bias[n + 1];
                __nv_bfloat162 h0, h1;
                h0.x = __float2bfloat16(fmaxf(v[0] + b0, 0.f));
                h0.y = __float2bfloat16(fmaxf(v[1] + b1, 0.f));
                h1.x = __float2bfloat16(fmaxf(v[2] + b0, 0.f));
                h1.y = __float2bfloat16(fmaxf(v[3] + b1, 0.f));
                *(__nv_bfloat162*)(H + ABLK_OFF(m0, n))     = h0;
                *(__nv_bfloat162*)(H + ABLK_OFF(m0 + 8, n)) = h1;
            } else {
                float* Cp = (float*)Cout + (size_t)blockIdx.y * partStride;
                *(float2*)&Cp[(size_t)m0 * KPAD + n]       = make_float2(v[0], v[1]);
                *(float2*)&Cp[(size_t)(m0 + 8) * KPAD + n] = make_float2(v[2], v[3]);
            }
        }
    }
}

// ------ scatter: G += g at (a_r,a_c),(a_c,a_r); g = sum8(parts)+b3 ----------
__global__ void k_scatter(const float* __restrict__ b3) {
    GD_LAUNCH; GD_WAIT;
    int i = blockIdx.x;
    int tid = threadIdx.x;   // 128
    __shared__ int a[81];
    for (int t = tid; t < 81; t += 128) a[t] = g_idx[i * 81 + t];
    __syncthreads();
    for (int k = tid; k < DIN; k += 128) {
        float v = b3[k];
        #pragma unroll
        for (int s = 0; s < 8; s++) v += g_parts[(size_t)s * NN * KPAD + i * KPAD + k];
        int r, c; mask_rc(k, r, c);
        atomicAdd(&g_G[a[r] * NN + a[c]], v);
        atomicAdd(&g_G[a[c] * NN + a[r]], v);
    }
}

// --------- Fbar = Gbar F; normalize-VJP; SGD update -------------------------
__global__ void k_update(int lo, float* __restrict__ target) {
    GD_LAUNCH; GD_WAIT;
    int p = lo + blockIdx.x;
    int tid = threadIdx.x;
    __shared__ float Gp[NN];
    __shared__ float fb[FEAT];
    __shared__ float red[256];
    for (int q = tid; q < NN; q += 256) Gp[q] = g_G[p * NN + q];
    __syncthreads();
    for (int d = tid; d < FEAT; d += 256) {
        float s = 0.f;
        #pragma unroll 8
        for (int q = 0; q < NN; q++) s += Gp[q] * g_F[q * FEAT + d];
        fb[d] = s;
    }
    __syncthreads();
    float part = 0.f;
    for (int d = tid; d < FEAT; d += 256) part += fb[d] * g_F[p * FEAT + d];
    red[tid] = part; __syncthreads();
    for (int o = 128; o > 0; o >>= 1) { if (tid < o) red[tid] += red[tid + o]; __syncthreads(); }
    float dot = red[0];
    float inv = 1.f / g_nrm[p];
    for (int d = tid; d < FEAT; d += 256) {
        float fp = g_F[p * FEAT + d];
        float dX = (fb[d] - dot * fp) * inv;
        target[(p - lo) * FEAT + d] -= LRC * dX;
    }
}

// ------------- final: normalize from raw + (sim_sq * scale)^T ---------------
__global__ void k_final(const float* __restrict__ scale, float* __restrict__ out) {
    GD_LAUNCH; GD_WAIT;
    int q = blockIdx.x;
    int tid = threadIdx.x;
    __shared__ float Fq[FEAT];
    __shared__ float red[256];
    const float* qr = g_query + q * FEAT;
    float s = 0.f;
    for (int d = tid; d < FEAT; d += 256) { float v = qr[d]; Fq[d] = v; s += v * v; }
    red[tid] = s; __syncthreads();
    for (int o = 128; o > 0; o >>= 1) { if (tid < o) red[tid] += red[tid + o]; __syncthreads(); }
    float nq = fmaxf(sqrtf(red[0]), 1e-12f);
    int w = tid >> 5, l = tid & 31;
    if (w < NCLS) {
        const float* sr = g_supp + w * FEAT;
        float dt = 0.f, s2 = 0.f;
        for (int d = l; d < FEAT; d += 32) {
            float sv = sr[d];
            dt += sv * Fq[d];
            s2 += sv * sv;
        }
        #pragma unroll
        for (int o = 16; o > 0; o >>= 1) {
            dt += __shfl_xor_sync(0xffffffffu, dt, o);
            s2 += __shfl_xor_sync(0xffffffffu, s2, o);
        }
        if (l == 0) {
            float ns = fmaxf(sqrtf(s2), 1e-12f);
            out[q * NCLS + w] = dt / (ns * nq) * scale[0];
        }
    }
}

// --------------------------- PDL launch helper ------------------------------
static inline void pdl_launch(const void* fn, dim3 gd, dim3 bd, size_t smem, void** args) {
    cudaLaunchConfig_t cfg = {};
    cfg.gridDim = gd;
    cfg.blockDim = bd;
    cfg.dynamicSmemBytes = smem;
    cfg.stream = 0;
    cudaLaunchAttribute at[1];
    at[0].id = cudaLaunchAttributeProgrammaticStreamSerialization;
    at[0].val.programmaticStreamSerializationAllowed = 1;
    cfg.attrs = at;
    cfg.numAttrs = 1;
    cudaLaunchKernelExC(&cfg, fn, args);
}

// ----------------------------------------------------------------------------
extern "C" void kernel_launch(void* const* d_in, const int* in_sizes, int n_in,
                              void* d_out, int out_size) {
    const float* fs    = (const float*)d_in[0];
    const float* fq    = (const float*)d_in[1];
    const float* scale = (const float*)d_in[2];

    float *pp, *ps, *pq;
    char *pxb, *ph1b, *ph2b, *pw1b, *pw2b, *pw3b;
    cudaGetSymbolAddress((void**)&pp,   g_parts);
    cudaGetSymbolAddress((void**)&ps,   g_supp);
    cudaGetSymbolAddress((void**)&pq,   g_query);
    cudaGetSymbolAddress((void**)&pxb,  g_xb);
    cudaGetSymbolAddress((void**)&ph1b, g_h1b);
    cudaGetSymbolAddress((void**)&ph2b, g_h2b);
    cudaGetSymbolAddress((void**)&pw1b, g_W1b);
    cudaGetSymbolAddress((void**)&pw2b, g_W2b);
    cudaGetSymbolAddress((void**)&pw3b, g_W3b);

    cudaFuncSetAttribute(k_gemmB<0>, cudaFuncAttributeMaxDynamicSharedMemorySize, GSMEM);
    cudaFuncSetAttribute(k_gemmB<1>, cudaFuncAttributeMaxDynamicSharedMemorySize, GSMEM);

    // first kernel: plain launch (its completion gates the PDL cascade)
    k_convinit<<<20 + CONVBLK, 256>>>(fs, fq,
        (const float*)d_in[3],  (const float*)d_in[5],  (const float*)d_in[7],
        (const float*)d_in[9],  (const float*)d_in[11], (const float*)d_in[13]);

    for (int step = 0; step < 3; step++) {
        for (int br = 0; br < 2; br++) {
            const float* b1 = (const float*)d_in[3 + 6 * br + 1];
            const float* b2 = (const float*)d_in[3 + 6 * br + 3];
            const float* b3 = (const float*)d_in[3 + 6 * br + 5];
            char* W1b = pw1b + (size_t)br * T1 * 2;
            char* W2b = pw2b + (size_t)br * T2 * 2;
            char* W3b = pw3b + (size_t)br * T3 * 2;
            int lo    = br ? NCLS : 0;
            int nrows = br ? NQ : NCLS;
            float* target = br ? pq : ps;

            pdl_launch((const void*)k_sim, dim3(NN), dim3(256), 0, nullptr);
            pdl_launch((const void*)k_sortgather, dim3(NN), dim3(128), 0, nullptr);

            {   // L1: K=512 (kgK=128, nIt=2), N=4096 -> 128 n-blocks
                const char* A = pxb; const char* W = W1b;
                int kbt = 8, kch = 512, pstr = 0;
                const float* bb = b1; void* C = ph1b;
                void* args[] = {&A, &W, &kbt, &kch, &bb, &C, &pstr};
                pdl_launch((const void*)k_gemmB<0>, dim3(128, 1), dim3(512), GSMEM, args);
            }
            {   // L2: K=4096 (kgK=1024, nIt=16), N=4096
                const char* A = ph1b; const char* W = W2b;
                int kbt = 64, kch = 4096, pstr = 0;
                const float* bb = b2; void* C = ph2b;
                void* args[] = {&A, &W, &kbt, &kch, &bb, &C, &pstr};
                pdl_launch((const void*)k_gemmB<0>, dim3(128, 1), dim3(512), GSMEM, args);
            }
            {   // L3: N=512 (16 n-blocks), splitK=8 (Kchunk=512)
                const char* A = ph2b; const char* W = W3b;
                int kbt = 64, kch = 512, pstr = NN * KPAD;
                const float* bb = nullptr; void* C = pp;
                void* args[] = {&A, &W, &kbt, &kch, &bb, &C, &pstr};
                pdl_launch((const void*)k_gemmB<1>, dim3(16, 8), dim3(512), GSMEM, args);
            }
            {
                const float* bb = b3;
                void* args[] = {&bb};
                pdl_launch((const void*)k_scatter, dim3(NN), dim3(128), 0, args);
            }
            {
                int lo_ = lo; float* tg = target;
                void* args[] = {&lo_, &tg};
                pdl_launch((const void*)k_update, dim3(nrows), dim3(256), 0, args);
            }
        }
    }

    {
        const float* sc = scale; float* ot = (float*)d_out;
        void* args[] = {&sc, &ot};
        pdl_launch((const void*)k_final, dim3(NQ), dim3(256), 0, args);
    }
}

// round 14
// speedup vs baseline: 1.2223x; 1.0623x over previous
#include <cuda_runtime.h>
#include <cuda_bf16.h>
#include <math.h>
#include <stdint.h>

#define NCLS 5
#define NQ   75
#define NN   80
#define FEAT 640
#define HID  4096
#define DIN  465
#define KPAD 512
#define LRC  1e-3f

// ------------------------- scratch (device globals) -------------------------
__device__ __align__(128) float g_supp[NCLS * FEAT];
__device__ __align__(128) float g_query[NQ * FEAT];
__device__ __align__(128) float g_F[NN * FEAT];          // normalized rows
__device__ float g_nrm[NN];
__device__ __align__(128) float g_sim[NN * NN];          // RAW dot products
__device__ int   g_idx[NN * 81];
__device__ __align__(128) float g_G[NN * NN];
__device__ __align__(128) float g_parts[2 * NN * HID];   // L2 splitK / L3 splitK partials
// activations, BLOCKED: A_blk[kb][80][64] bf16, SW128-swizzled 128B rows
__device__ __align__(1024) __nv_bfloat16 g_xb [NN * KPAD];
__device__ __align__(1024) __nv_bfloat16 g_h1b[NN * HID];
__device__ __align__(1024) __nv_bfloat16 g_h2b[NN * HID];
// weights, BLOCKED: W_blk[nt][kb][32][64] bf16, SW128-swizzled (nt = n/32)
__device__ __align__(1024) __nv_bfloat16 g_W1b[2][HID * KPAD];
__device__ __align__(1024) __nv_bfloat16 g_W2b[2][HID * HID];
__device__ __align__(1024) __nv_bfloat16 g_W3b[2][KPAD * HID];

#define SW128(o) ((o) ^ (((o) >> 3) & 0x70))
#define ABLK_OFF(m, k) (((k) >> 6) * 10240u + SW128((uint32_t)(((m) << 7) | (((k) & 63) << 1))))

// PDL intrinsics (sm_90+)
#define GD_LAUNCH asm volatile("griddepcontrol.launch_dependents;")
#define GD_WAIT   asm volatile("griddepcontrol.wait;" ::: "memory")

__device__ __forceinline__ void mask_rc(int k, int& r, int& c) {
    int base;
    if      (k < 80)  { r = 0; base = 0;   }
    else if (k < 159) { r = 1; base = 80;  }
    else if (k < 237) { r = 2; base = 159; }
    else if (k < 314) { r = 3; base = 237; }
    else if (k < 390) { r = 4; base = 314; }
    else              { r = 5; base = 390; }
    c = r + 1 + (k - base);
}

// ------------------------- PTX helpers --------------------------------------
__device__ __forceinline__ uint32_t s_u32(const void* p) {
    return (uint32_t)__cvta_generic_to_shared(p);
}
__device__ __forceinline__ void ldsm_x4(uint32_t* r, uint32_t addr) {
    asm volatile("ldmatrix.sync.aligned.m8n8.x4.shared.b16 {%0,%1,%2,%3}, [%4];"
        : "=r"(r[0]), "=r"(r[1]), "=r"(r[2]), "=r"(r[3]) : "r"(addr));
}
__device__ __forceinline__ void ldsm_x2(uint32_t* r, uint32_t addr) {
    asm volatile("ldmatrix.sync.aligned.m8n8.x2.shared.b16 {%0,%1}, [%2];"
        : "=r"(r[0]), "=r"(r[1]) : "r"(addr));
}
__device__ __forceinline__ void mma_bf16(float* d, const uint32_t* a, const uint32_t* b) {
    asm volatile("mma.sync.aligned.m16n8k16.row.col.f32.bf16.bf16.f32 "
        "{%0,%1,%2,%3}, {%4,%5,%6,%7}, {%8,%9}, {%0,%1,%2,%3};"
        : "+f"(d[0]), "+f"(d[1]), "+f"(d[2]), "+f"(d[3])
        : "r"(a[0]), "r"(a[1]), "r"(a[2]), "r"(a[3]), "r"(b[0]), "r"(b[1]));
}
__device__ __forceinline__ void bulkcp(uint32_t dst, const void* src, uint32_t bytes,
                                       uint32_t mbar) {
    asm volatile(
        "cp.async.bulk.shared::cluster.global.mbarrier::complete_tx::bytes [%0], [%1], %2, [%3];"
        :: "r"(dst), "l"(src), "r"(bytes), "r"(mbar) : "memory");
}
__device__ __forceinline__ void mbar_init(uint32_t mbar, uint32_t cnt) {
    asm volatile("mbarrier.init.shared.b64 [%0], %1;" :: "r"(mbar), "r"(cnt) : "memory");
}
__device__ __forceinline__ void mbar_expect(uint32_t mbar, uint32_t tx) {
    asm volatile("mbarrier.arrive.expect_tx.shared.b64 _, [%0], %1;"
                 :: "r"(mbar), "r"(tx) : "memory");
}
#define MWAIT(addr, ph) do { \
    uint32_t _d = 0; \
    while (!_d) { \
        asm volatile("{\n\t.reg .pred p;\n\t" \
            "mbarrier.try_wait.parity.acquire.cta.shared::cta.b64 p, [%1], %2;\n\t" \
            "selp.b32 %0, 1, 0, p;\n\t}" : "=r"(_d) : "r"(addr), "r"(ph)); \
    } } while (0)

// ---- merged FIRST kernel: blocks 0..19 init raw rows, rest convert weights -
#define T1 2097152
#define T2 16777216
#define T3 2097152
#define CONVBLK 20480
__global__ void k_convinit(const float* fs, const float* fq,
                           const float* s0, const float* s1, const float* s2,
                           const float* s3, const float* s4, const float* s5) {
    if (blockIdx.x < 20) {
        for (int idx = blockIdx.x * 256 + threadIdx.x; idx < NN * FEAT; idx += 20 * 256) {
            int r = idx / FEAT, d = idx % FEAT;
            if (r < NCLS) {
                float s = 0.f;
                #pragma unroll
                for (int sh = 0; sh < 5; sh++) s += fs[(r * 5 + sh) * FEAT + d];
                g_supp[r * FEAT + d] = s / 5.0f;
            } else {
                g_query[(r - NCLS) * FEAT + d] = fq[(r - NCLS) * FEAT + d];
            }
        }
        return;
    }
    long long e = ((long long)(blockIdx.x - 20) * 256 + threadIdx.x) * 8;
    const float* src; char* dst; long long local; int type;
    if      (e < T1)           { src = s0; dst = (char*)g_W1b[0]; local = e;                  type = 0; }
    else if (e < T1+T2)        { src = s1; dst = (char*)g_W2b[0]; local = e - T1;             type = 1; }
    else if (e < T1+T2+T3)     { src = s2; dst = (char*)g_W3b[0]; local = e - (T1+T2);        type = 2; }
    else if (e < 2*T1+T2+T3)   { src = s3; dst = (char*)g_W1b[1]; local = e - (T1+T2+T3);     type = 0; }
    else if (e < 2*T1+2*T2+T3) { src = s4; dst = (char*)g_W2b[1]; local = e - (2*T1+T2+T3);   type = 1; }
    else                       { src = s5; dst = (char*)g_W3b[1]; local = e - (2*T1+2*T2+T3); type = 2; }
    int K = (type == 0) ? 512 : 4096;
    int n = (int)(local / K);
    int k = (int)(local - (long long)n * K);
    float v[8];
    #pragma unroll
    for (int j = 0; j < 8; j++) {
        bool ok = (type == 0) ? (k + j < DIN) : (type == 2 ? (n < DIN) : true);
        int cols = (type == 0) ? DIN : 4096;
        v[j] = ok ? src[(size_t)n * cols + k + j] : 0.f;
    }
    uint32_t off = ((uint32_t)(n >> 5) * (uint32_t)(K >> 6) + (uint32_t)(k >> 6)) * 4096u
                 + SW128((uint32_t)(((n & 31) << 7) | ((k & 63) << 1)));
    uint32_t o[4];
    #pragma unroll
    for (int j = 0; j < 4; j++) {
        __nv_bfloat162 h;
        h.x = __float2bfloat16(v[2 * j]);
        h.y = __float2bfloat16(v[2 * j + 1]);
        o[j] = *(uint32_t*)&h;
    }
    *(uint4*)(dst + off) = make_uint4(o[0], o[1], o[2], o[3]);
}

// ---------- sim: raw Gram row + own norm + normalized F row -----------------
__global__ void k_sim() {
    GD_LAUNCH; GD_WAIT;
    int i = blockIdx.x;
    int tid = threadIdx.x;
    __shared__ float Fi[FEAT];
    __shared__ float red[256];
    const float* src = (i < NCLS) ? (g_supp + i * FEAT) : (g_query + (i - NCLS) * FEAT);
    float s = 0.f;
    for (int d = tid; d < FEAT; d += 256) { float v = src[d]; Fi[d] = v; s += v * v; }
    red[tid] = s; __syncthreads();
    for (int o = 128; o > 0; o >>= 1) { if (tid < o) red[tid] += red[tid + o]; __syncthreads(); }
    float nrm = fmaxf(sqrtf(red[0]), 1e-12f);
    if (tid == 0) g_nrm[i] = nrm;
    float inv = 1.f / nrm;
    for (int d = tid; d < FEAT; d += 256) g_F[i * FEAT + d] = Fi[d] * inv;
    int w = tid >> 5, l = tid & 31;
    for (int j = w; j < NN; j += 8) {
        const float* Xj = (j < NCLS) ? (g_supp + j * FEAT) : (g_query + (j - NCLS) * FEAT);
        float p = 0.f;
        for (int d = l; d < FEAT; d += 32) p += Fi[d] * Xj[d];
        #pragma unroll
        for (int o = 16; o > 0; o >>= 1) p += __shfl_xor_sync(0xffffffffu, p, o);
        if (l == 0) g_sim[i * NN + j] = p;
    }
}

// ------- stable rank sort + gather DNI inputs into BLOCKED bf16 -------------
__global__ void k_sortgather() {
    GD_LAUNCH; GD_WAIT;
    int i = blockIdx.x;
    int tid = threadIdx.x;   // 128
    __shared__ float srow[NN];
    __shared__ float inv[NN];
    __shared__ int a[81];
    for (int j = tid; j < NN; j += 128) inv[j] = 1.f / g_nrm[j];
    __syncthreads();
    float invi = inv[i];
    for (int j = tid; j < NN; j += 128) srow[j] = g_sim[i * NN + j] * invi * inv[j];
    if (tid == 0) a[0] = i;
    __syncthreads();
    if (tid < NCLS) {
        float v = srow[tid];
        int rank = 0;
        #pragma unroll
        for (int j = 0; j < NCLS; j++) {
            float u = srow[j];
            if (j != tid && (u > v || (u == v && j < tid))) rank++;
        }
        a[1 + rank] = tid;
    }
    if (tid < NQ) {
        float v = srow[NCLS + tid];
        int rank = 0;
        for (int j = 0; j < NQ; j++) {
            float u = srow[NCLS + j];
            if (u > v || (u == v && j < tid)) rank++;
        }
        a[6 + rank] = NCLS + tid;
    }
    __syncthreads();
    for (int t = tid; t < 81; t += 128) g_idx[i * 81 + t] = a[t];
    char* xb = (char*)g_xb;
    for (int k = tid; k < KPAD; k += 128) {
        float v = 0.f;
        if (k < DIN) {
            int r, c; mask_rc(k, r, c);
            v = g_sim[a[r] * NN + a[c]] * inv[a[r]] * inv[a[c]];
        }
        *(__nv_bfloat16*)(xb + ABLK_OFF(i, k)) = __float2bfloat16(v);
    }
    for (int t = tid; t < NN; t += 128) g_G[i * NN + t] = 0.f;
}

// ========= BN=32 GEMM (L1 / L3): 512 thr, 4 kgroups x 4 n-warps =============
#define KGB 14336
#define STB 57344
#define GSMEM (3 * STB + 1024)
template<int MODE>
__global__ void __launch_bounds__(512) k_gemmB(
    const char* __restrict__ Ablk, const char* __restrict__ Wblk,
    int KbTotal, int Kchunk, const float* __restrict__ bias,
    void* __restrict__ Cout, int partStride)
{
    extern __shared__ char dyn[];
    __shared__ uint64_t mbarW[3], mbarA[3];
    GD_LAUNCH;
    const int tid = threadIdx.x, w = tid >> 5, l = tid & 31;
    const int kg = w >> 2, nw = w & 3;
    const int nb = blockIdx.x;
    const int k0 = blockIdx.y * Kchunk;
    const int kgK = Kchunk >> 2;
    const int nIt = kgK >> 6;
    const uint32_t sbase = (s_u32(dyn) + 1023u) & ~1023u;
    char* dalign = (char*)(((uintptr_t)dyn + 1023ull) & ~1023ull);

    if (tid == 0) {
        #pragma unroll
        for (int i = 0; i < 3; i++) {
            mbar_init(s_u32(&mbarW[i]), 1);
            mbar_init(s_u32(&mbarA[i]), 1);
        }
    }
    __syncthreads();

    auto issueW = [&](int it, int s) {
        uint32_t st = sbase + s * STB;
        uint32_t mb = s_u32(&mbarW[s]);
        mbar_expect(mb, 4 * 4096);
        #pragma unroll
        for (int g = 0; g < 4; g++) {
            int kb = ((k0 + g * kgK) >> 6) + it;
            bulkcp(st + g * KGB + 10240, Wblk + ((size_t)nb * KbTotal + kb) * 4096, 4096, mb);
        }
    };
    auto issueA = [&](int it, int s) {
        uint32_t st = sbase + s * STB;
        uint32_t mb = s_u32(&mbarA[s]);
        mbar_expect(mb, 4 * 10240);
        #pragma unroll
        for (int g = 0; g < 4; g++) {
            int kb = ((k0 + g * kgK) >> 6) + it;
            bulkcp(st + g * KGB, Ablk + (size_t)kb * 10240, 10240, mb);
        }
    };

    int npre = (nIt < 3) ? nIt : 3;
    if (tid == 0)
        for (int c = 0; c < npre; c++) issueW(c, c);   // W static: pre-wait prefetch
    GD_WAIT;
    if (tid == 0)
        for (int c = 0; c < npre; c++) issueA(c, c);

    float acc[5][4];
    #pragma unroll
    for (int mt = 0; mt < 5; mt++)
        #pragma unroll
        for (int q = 0; q < 4; q++) acc[mt][q] = 0.f;

    const int arow = (l & 7) + 8 * ((l >> 3) & 1);
    const int acolB = 16 * (l >> 4);
    const int brow = (l & 7);
    const int bcolB = 16 * ((l >> 3) & 1);

    int phW[3] = {0, 0, 0}, phA[3] = {0, 0, 0};
    for (int it = 0; it < nIt; it++) {
        int s = it % 3;
        MWAIT(s_u32(&mbarW[s]), phW[s]); phW[s] ^= 1;
        MWAIT(s_u32(&mbarA[s]), phA[s]); phA[s] ^= 1;
        uint32_t A0 = sbase + s * STB + kg * KGB;
        uint32_t W0 = A0 + 10240;
        #pragma unroll
        for (int ks = 0; ks < 4; ks++) {
            uint32_t kb = ks * 32;
            uint32_t b[2];
            ldsm_x2(b, W0 + SW128((uint32_t)((nw * 8 + brow) * 128) + kb + bcolB));
            #pragma unroll
            for (int mt = 0; mt < 5; mt++) {
                uint32_t a[4];
                ldsm_x4(a, A0 + SW128((uint32_t)((mt * 16 + arow) * 128) + kb + acolB));
                mma_bf16(acc[mt], a, b);
            }
        }
        __syncthreads();
        if (tid == 0 && it + 3 < nIt) { issueW(it + 3, s); issueA(it + 3, s); }
    }

    float* scr = (float*)dalign;   // 3 x 2560 floats
    __syncthreads();
    if (kg > 0) {
        float* sp = scr + (kg - 1) * 2560;
        #pragma unroll
        for (int mt = 0; mt < 5; mt++)
            #pragma unroll
            for (int q = 0; q < 4; q++)
                sp[((nw * 5 + mt) * 32 + l) * 4 + q] = acc[mt][q];
    }
    __syncthreads();
    if (kg == 0) {
        int n = nb * 32 + nw * 8 + 2 * (l & 3);
        #pragma unroll
        for (int mt = 0; mt < 5; mt++) {
            float v[4];
            #pragma unroll
            for (int q = 0; q < 4; q++) {
                int idx = ((nw * 5 + mt) * 32 + l) * 4 + q;
                v[q] = acc[mt][q] + scr[idx] + scr[2560 + idx] + scr[5120 + idx];
            }
            int m0 = mt * 16 + (l >> 2);
            if (MODE == 0) {
                char* H = (char*)Cout;
                float b0 = bias[n], b1 = bias[n + 1];
                __nv_bfloat162 h0, h1;
                h0.x = __float2bfloat16(fmaxf(v[0] + b0, 0.f));
                h0.y = __float2bfloat16(fmaxf(v[1] + b1, 0.f));
                h1.x = __float2bfloat16(fmaxf(v[2] + b0, 0.f));
                h1.y = __float2bfloat16(fmaxf(v[3] + b1, 0.f));
                *(__nv_bfloat162*)(H + ABLK_OFF(m0, n))     = h0;
                *(__nv_bfloat162*)(H + ABLK_OFF(m0 + 8, n)) = h1;
            } else {
                float* Cp = (float*)Cout + (size_t)blockIdx.y * partStride;
                *(float2*)&Cp[(size_t)m0 * KPAD + n]       = make_float2(v[0], v[1]);
                *(float2*)&Cp[(size_t)(m0 + 8) * KPAD + n] = make_float2(v[2], v[3]);
            }
        }
    }
}

// ==== BN=64 GEMM (L2): grid (64 nb, 2 sk), fp32 partials; A-traffic halved ==
#define KGB64 18432
#define STB64 73728
#define GSMEM64 (3 * STB64 + 1024)
__global__ void __launch_bounds__(512) k_gemm64(
    const char* __restrict__ Ablk, const char* __restrict__ Wblk,
    int KbTotal, int Kchunk, float* __restrict__ Cout, int partStride)
{
    extern __shared__ char dyn[];
    __shared__ uint64_t mbarW[3], mbarA[3];
    GD_LAUNCH;
    const int tid = threadIdx.x, w = tid >> 5, l = tid & 31;
    const int kg = w >> 2, nw = w & 3;
    const int nb = blockIdx.x;
    const int k0 = blockIdx.y * Kchunk;
    const int kgK = Kchunk >> 2;
    const int nIt = kgK >> 6;
    const uint32_t sbase = (s_u32(dyn) + 1023u) & ~1023u;
    char* dalign = (char*)(((uintptr_t)dyn + 1023ull) & ~1023ull);

    if (tid == 0) {
        #pragma unroll
        for (int i = 0; i < 3; i++) {
            mbar_init(s_u32(&mbarW[i]), 1);
            mbar_init(s_u32(&mbarA[i]), 1);
        }
    }
    __syncthreads();

    auto issueW = [&](int it, int s) {
        uint32_t st = sbase + s * STB64;
        uint32_t mb = s_u32(&mbarW[s]);
        mbar_expect(mb, 8 * 4096);
        #pragma unroll
        for (int g = 0; g < 4; g++) {
            int kb = ((k0 + g * kgK) >> 6) + it;
            bulkcp(st + g * KGB64 + 10240,
                   Wblk + ((size_t)(nb * 2)     * KbTotal + kb) * 4096, 4096, mb);
            bulkcp(st + g * KGB64 + 14336,
                   Wblk + ((size_t)(nb * 2 + 1) * KbTotal + kb) * 4096, 4096, mb);
        }
    };
    auto issueA = [&](int it, int s) {
        uint32_t st = sbase + s * STB64;
        uint32_t mb = s_u32(&mbarA[s]);
        mbar_expect(mb, 4 * 10240);
        #pragma unroll
        for (int g = 0; g < 4; g++) {
            int kb = ((k0 + g * kgK) >> 6) + it;
            bulkcp(st + g * KGB64, Ablk + (size_t)kb * 10240, 10240, mb);
        }
    };

    int npre = (nIt < 3) ? nIt : 3;
    if (tid == 0)
        for (int c = 0; c < npre; c++) issueW(c, c);
    GD_WAIT;
    if (tid == 0)
        for (int c = 0; c < npre; c++) issueA(c, c);

    float acc[5][2][4];
    #pragma unroll
    for (int mt = 0; mt < 5; mt++)
        #pragma unroll
        for (int j = 0; j < 2; j++)
            #pragma unroll
            for (int q = 0; q < 4; q++) acc[mt][j][q] = 0.f;

    const int arow = (l & 7) + 8 * ((l >> 3) & 1);
    const int acolB = 16 * (l >> 4);
    const int wrow = (nw & 1) * 16 + ((l >> 4) << 3) + (l & 7);
    const int wcolB = 16 * ((l >> 3) & 1);
    const uint32_t wtile = (uint32_t)(nw >> 1) * 4096u;

    int phW[3] = {0, 0, 0}, phA[3] = {0, 0, 0};
    for (int it = 0; it < nIt; it++) {
        int s = it % 3;
        MWAIT(s_u32(&mbarW[s]), phW[s]); phW[s] ^= 1;
        MWAIT(s_u32(&mbarA[s]), phA[s]); phA[s] ^= 1;
        uint32_t A0 = sbase + s * STB64 + kg * KGB64;
        uint32_t W0 = A0 + 10240 + wtile;
        #pragma unroll
        for (int ks = 0; ks < 4; ks++) {
            uint32_t kb = ks * 32;
            uint32_t b[4];
            ldsm_x4(b, W0 + SW128((uint32_t)(wrow << 7) + kb + wcolB));
            #pragma unroll
            for (int mt = 0; mt < 5; mt++) {
                uint32_t a[4];
                ldsm_x4(a, A0 + SW128((uint32_t)((mt * 16 + arow) << 7) + kb + acolB));
                mma_bf16(acc[mt][0], a, b);
                mma_bf16(acc[mt][1], a, b + 2);
            }
        }
        __syncthreads();
        if (tid == 0 && it + 3 < nIt) { issueW(it + 3, s); issueA(it + 3, s); }
    }

    float* scr = (float*)dalign;   // 3 x 5120 floats
    __syncthreads();
    if (kg > 0) {
        float* sp = scr + (kg - 1) * 5120;
        #pragma unroll
        for (int mt = 0; mt < 5; mt++)
            #pragma unroll
            for (int j = 0; j < 2; j++)
                #pragma unroll
                for (int q = 0; q < 4; q++)
                    sp[(((nw * 5 + mt) * 2 + j) * 32 + l) * 4 + q] = acc[mt][j][q];
    }
    __syncthreads();
    if (kg == 0) {
        float* Cp = Cout + (size_t)blockIdx.y * partStride;
        #pragma unroll
        for (int mt = 0; mt < 5; mt++) {
            #pragma unroll
            for (int j = 0; j < 2; j++) {
                int n = nb * 64 + nw * 16 + j * 8 + 2 * (l & 3);
                int m0 = mt * 16 + (l >> 2);
                float v[4];
                #pragma unroll
                for (int q = 0; q < 4; q++) {
                    int idx = (((nw * 5 + mt) * 2 + j) * 32 + l) * 4 + q;
                    v[q] = acc[mt][j][q] + scr[idx] + scr[5120 + idx] + scr[10240 + idx];
                }
                *(float2*)&Cp[(size_t)m0 * HID + n]       = make_float2(v[0], v[1]);
                *(float2*)&Cp[(size_t)(m0 + 8) * HID + n] = make_float2(v[2], v[3]);
            }
        }
    }
}

// ---- combine L2 splitK=2: h2 = bf16(relu(p0+p1+bias)) in blocked layout ----
__global__ void k_comb2(const float* __restrict__ bias) {
    GD_LAUNCH; GD_WAIT;
    int m = blockIdx.x;              // 80 blocks x 256
    char* H = (char*)g_h2b;
    const float* p0 = g_parts + (size_t)m * HID;
    const float* p1 = g_parts + (size_t)NN * HID + (size_t)m * HID;
    for (int n = threadIdx.x * 2; n < HID; n += 512) {
        float2 a = *(const float2*)&p0[n];
        float2 b = *(const float2*)&p1[n];
        __nv_bfloat162 h;
        h.x = __float2bfloat16(fmaxf(a.x + b.x + bias[n], 0.f));
        h.y = __float2bfloat16(fmaxf(a.y + b.y + bias[n + 1], 0.f));
        *(__nv_bfloat162*)(H + ABLK_OFF(m, n)) = h;
    }
}

// ------ scatter: G += g at (a_r,a_c),(a_c,a_r); g = sum8(parts)+b3 ----------
__global__ void k_scatter(const float* __restrict__ b3) {
    GD_LAUNCH; GD_WAIT;
    int i = blockIdx.x;
    int tid = threadIdx.x;   // 128
    __shared__ int a[81];
    for (int t = tid; t < 81; t += 128) a[t] = g_idx[i * 81 + t];
    __syncthreads();
    for (int k = tid; k < DIN; k += 128) {
        float v = b3[k];
        #pragma unroll
        for (int s = 0; s < 8; s++) v += g_parts[(size_t)s * NN * KPAD + i * KPAD + k];
        int r, c; mask_rc(k, r, c);
        atomicAdd(&g_G[a[r] * NN + a[c]], v);
        atomicAdd(&g_G[a[c] * NN + a[r]], v);
    }
}

// --------- Fbar = Gbar F; normalize-VJP; SGD update -------------------------
__global__ void k_update(int lo, float* __restrict__ target) {
    GD_LAUNCH; GD_WAIT;
    int p = lo + blockIdx.x;
    int tid = threadIdx.x;
    __shared__ float Gp[NN];
    __shared__ float fb[FEAT];
    __shared__ float red[256];
    for (int q = tid; q < NN; q += 256) Gp[q] = g_G[p * NN + q];
    __syncthreads();
    for (int d = tid; d < FEAT; d += 256) {
        float s = 0.f;
        #pragma unroll 8
        for (int q = 0; q < NN; q++) s += Gp[q] * g_F[q * FEAT + d];
        fb[d] = s;
    }
    __syncthreads();
    float part = 0.f;
    for (int d = tid; d < FEAT; d += 256) part += fb[d] * g_F[p * FEAT + d];
    red[tid] = part; __syncthreads();
    for (int o = 128; o > 0; o >>= 1) { if (tid < o) red[tid] += red[tid + o]; __syncthreads(); }
    float dot = red[0];
    float inv = 1.f / g_nrm[p];
    for (int d = tid; d < FEAT; d += 256) {
        float fp = g_F[p * FEAT + d];
        float dX = (fb[d] - dot * fp) * inv;
        target[(p - lo) * FEAT + d] -= LRC * dX;
    }
}

// ------------- final: normalize from raw + (sim_sq * scale)^T ---------------
__global__ void k_final(const float* __restrict__ scale, float* __restrict__ out) {
    GD_LAUNCH; GD_WAIT;
    int q = blockIdx.x;
    int tid = threadIdx.x;
    __shared__ float Fq[FEAT];
    __shared__ float red[256];
    const float* qr = g_query + q * FEAT;
    float s = 0.f;
    for (int d = tid; d < FEAT; d += 256) { float v = qr[d]; Fq[d] = v; s += v * v; }
    red[tid] = s; __syncthreads();
    for (int o = 128; o > 0; o >>= 1) { if (tid < o) red[tid] += red[tid + o]; __syncthreads(); }
    float nq = fmaxf(sqrtf(red[0]), 1e-12f);
    int w = tid >> 5, l = tid & 31;
    if (w < NCLS) {
        const float* sr = g_supp + w * FEAT;
        float dt = 0.f, s2 = 0.f;
        for (int d = l; d < FEAT; d += 32) {
            float sv = sr[d];
            dt += sv * Fq[d];
            s2 += sv * sv;
        }
        #pragma unroll
        for (int o = 16; o > 0; o >>= 1) {
            dt += __shfl_xor_sync(0xffffffffu, dt, o);
            s2 += __shfl_xor_sync(0xffffffffu, s2, o);
        }
        if (l == 0) {
            float ns = fmaxf(sqrtf(s2), 1e-12f);
            out[q * NCLS + w] = dt / (ns * nq) * scale[0];
        }
    }
}

// --------------------------- PDL launch helper ------------------------------
static inline void pdl_launch(const void* fn, dim3 gd, dim3 bd, size_t smem, void** args) {
    cudaLaunchConfig_t cfg = {};
    cfg.gridDim = gd;
    cfg.blockDim = bd;
    cfg.dynamicSmemBytes = smem;
    cfg.stream = 0;
    cudaLaunchAttribute at[1];
    at[0].id = cudaLaunchAttributeProgrammaticStreamSerialization;
    at[0].val.programmaticStreamSerializationAllowed = 1;
    cfg.attrs = at;
    cfg.numAttrs = 1;
    cudaLaunchKernelExC(&cfg, fn, args);
}

// ----------------------------------------------------------------------------
extern "C" void kernel_launch(void* const* d_in, const int* in_sizes, int n_in,
                              void* d_out, int out_size) {
    const float* fs    = (const float*)d_in[0];
    const float* fq    = (const float*)d_in[1];
    const float* scale = (const float*)d_in[2];

    float *pp, *ps, *pq;
    char *pxb, *ph1b, *ph2b, *pw1b, *pw2b, *pw3b;
    cudaGetSymbolAddress((void**)&pp,   g_parts);
    cudaGetSymbolAddress((void**)&ps,   g_supp);
    cudaGetSymbolAddress((void**)&pq,   g_query);
    cudaGetSymbolAddress((void**)&pxb,  g_xb);
    cudaGetSymbolAddress((void**)&ph1b, g_h1b);
    cudaGetSymbolAddress((void**)&ph2b, g_h2b);
    cudaGetSymbolAddress((void**)&pw1b, g_W1b);
    cudaGetSymbolAddress((void**)&pw2b, g_W2b);
    cudaGetSymbolAddress((void**)&pw3b, g_W3b);

    cudaFuncSetAttribute(k_gemmB<0>, cudaFuncAttributeMaxDynamicSharedMemorySize, GSMEM);
    cudaFuncSetAttribute(k_gemmB<1>, cudaFuncAttributeMaxDynamicSharedMemorySize, GSMEM);
    cudaFuncSetAttribute(k_gemm64,  cudaFuncAttributeMaxDynamicSharedMemorySize, GSMEM64);

    // first kernel: plain launch (its completion gates the PDL cascade)
    k_convinit<<<20 + CONVBLK, 256>>>(fs, fq,
        (const float*)d_in[3],  (const float*)d_in[5],  (const float*)d_in[7],
        (const float*)d_in[9],  (const float*)d_in[11], (const float*)d_in[13]);

    for (int step = 0; step < 3; step++) {
        for (int br = 0; br < 2; br++) {
            const float* b1 = (const float*)d_in[3 + 6 * br + 1];
            const float* b2 = (const float*)d_in[3 + 6 * br + 3];
            const float* b3 = (const float*)d_in[3 + 6 * br + 5];
            char* W1b = pw1b + (size_t)br * T1 * 2;
            char* W2b = pw2b + (size_t)br * T2 * 2;
            char* W3b = pw3b + (size_t)br * T3 * 2;
            int lo    = br ? NCLS : 0;
            int nrows = br ? NQ : NCLS;
            float* target = br ? pq : ps;

            pdl_launch((const void*)k_sim, dim3(NN), dim3(256), 0, nullptr);
            pdl_launch((const void*)k_sortgather, dim3(NN), dim3(128), 0, nullptr);

            {   // L1: BN=32, K=512 full, N=4096 -> 128 n-blocks
                const char* A = pxb; const char* W = W1b;
                int kbt = 8, kch = 512, pstr = 0;
                const float* bb = b1; void* C = ph1b;
                void* args[] = {&A, &W, &kbt, &kch, &bb, &C, &pstr};
                pdl_launch((const void*)k_gemmB<0>, dim3(128, 1), dim3(512), GSMEM, args);
            }
            {   // L2: BN=64, grid (64, 2) splitK, fp32 partials
                const char* A = ph1b; const char* W = W2b;
                int kbt = 64, kch = 2048, pstr = NN * HID;
                float* C = pp;
                void* args[] = {&A, &W, &kbt, &kch, &C, &pstr};
                pdl_launch((const void*)k_gemm64, dim3(64, 2), dim3(512), GSMEM64, args);
            }
            {   // combine L2 partials -> h2 (bias+relu, blocked bf16)
                const float* bb = b2;
                void* args[] = {&bb};
                pdl_launch((const void*)k_comb2, dim3(NN), dim3(256), 0, args);
            }
            {   // L3: BN=32, N=512 (16 n-blocks), splitK=8 (Kchunk=512)
                const char* A = ph2b; const char* W = W3b;
                int kbt = 64, kch = 512, pstr = NN * KPAD;
                const float* bb = nullptr; void* C = pp;
                void* args[] = {&A, &W, &kbt, &kch, &bb, &C, &pstr};
                pdl_launch((const void*)k_gemmB<1>, dim3(16, 8), dim3(512), GSMEM, args);
            }
            {
                const float* bb = b3;
                void* args[] = {&bb};
                pdl_launch((const void*)k_scatter, dim3(NN), dim3(128), 0, args);
            }
            {
                int lo_ = lo; float* tg = target;
                void* args[] = {&lo_, &tg};
                pdl_launch((const void*)k_update, dim3(nrows), dim3(256), 0, args);
            }
        }
    }

    {
        const float* sc = scale; float* ot = (float*)d_out;
        void* args[] = {&sc, &ot};
        pdl_launch((const void*)k_final, dim3(NQ), dim3(256), 0, args);
    }
}